// round 10
// baseline (speedup 1.0000x reference)
#include <cuda_runtime.h>
#include <cuda_bf16.h>
#include <math.h>
#include <stdint.h>

// Problem constants
#define BB 64
#define TT 1024
#define DD 128
#define HH 256

// Scratch ping-pong buffers [B*T*H] fp32 (64 MB each)
__device__ float g_bufA[(size_t)BB * TT * HH];
__device__ float g_bufB[(size_t)BB * TT * HH];

// ---------------------------------------------------------------------------
// GEMM: C[M,N] = A[M,K] @ W[N,K]^T + b1[n] + b2[n]
// BM=128, BN=128, BK=16, 256 threads, TM=8, TN=8, packed f32x2 accumulators.
// (unchanged from R4 — passing)
// ---------------------------------------------------------------------------
__global__ __launch_bounds__(256)
void gemm_bias_kernel(const float* __restrict__ A,
                      const float* __restrict__ W,
                      const float* __restrict__ b1,
                      const float* __restrict__ b2,
                      float* __restrict__ C,
                      int M, int N, int K)
{
    __shared__ float As[16][128];
    __shared__ float Ws[16][128];

    const int m0 = blockIdx.y * 128;
    const int n0 = blockIdx.x * 128;
    const int tid = threadIdx.x;
    const int tr = tid >> 4;
    const int tc = tid & 15;

    uint64_t acc2[8][4];
#pragma unroll
    for (int i = 0; i < 8; i++)
#pragma unroll
        for (int l = 0; l < 4; l++) acc2[i][l] = 0ull;

    for (int k0 = 0; k0 < K; k0 += 16) {
#pragma unroll
        for (int it = 0; it < 2; it++) {
            int id  = tid + it * 256;
            int row = id >> 2;
            int c4  = (id & 3) << 2;
            float4 v = *(const float4*)&A[(size_t)(m0 + row) * K + k0 + c4];
            As[c4 + 0][row] = v.x;
            As[c4 + 1][row] = v.y;
            As[c4 + 2][row] = v.z;
            As[c4 + 3][row] = v.w;
        }
#pragma unroll
        for (int it = 0; it < 2; it++) {
            int id  = tid + it * 256;
            int row = id >> 2;
            int c4  = (id & 3) << 2;
            float4 v = *(const float4*)&W[(size_t)(n0 + row) * K + k0 + c4];
            Ws[c4 + 0][row] = v.x;
            Ws[c4 + 1][row] = v.y;
            Ws[c4 + 2][row] = v.z;
            Ws[c4 + 3][row] = v.w;
        }
        __syncthreads();

#pragma unroll
        for (int k = 0; k < 16; k++) {
            float a[8];
#pragma unroll
            for (int i = 0; i < 8; i++) a[i] = As[k][tr * 8 + i];
            uint64_t w2[4];
            const uint64_t* wp = (const uint64_t*)&Ws[k][tc * 8];
#pragma unroll
            for (int l = 0; l < 4; l++) w2[l] = wp[l];
#pragma unroll
            for (int i = 0; i < 8; i++) {
                uint64_t a2;
                asm("mov.b64 %0, {%1, %1};" : "=l"(a2) : "f"(a[i]));
#pragma unroll
                for (int l = 0; l < 4; l++)
                    asm("fma.rn.f32x2 %0, %1, %2, %0;"
                        : "+l"(acc2[i][l]) : "l"(a2), "l"(w2[l]));
            }
        }
        __syncthreads();
    }

    float bb[8];
#pragma unroll
    for (int l = 0; l < 8; l++) {
        int n = n0 + tc * 8 + l;
        bb[l] = b1[n] + b2[n];
    }
#pragma unroll
    for (int i = 0; i < 8; i++) {
        float r[8];
#pragma unroll
        for (int l = 0; l < 4; l++) {
            uint32_t lo, hi;
            asm("mov.b64 {%0, %1}, %2;" : "=r"(lo), "=r"(hi) : "l"(acc2[i][l]));
            r[2 * l]     = __uint_as_float(lo) + bb[2 * l];
            r[2 * l + 1] = __uint_as_float(hi) + bb[2 * l + 1];
        }
        float* crow = &C[(size_t)(m0 + tr * 8 + i) * N + n0 + tc * 8];
        *(float4*)crow       = make_float4(r[0], r[1], r[2], r[3]);
        *(float4*)(crow + 4) = make_float4(r[4], r[5], r[6], r[7]);
    }
}

// ---------------------------------------------------------------------------
// Recurrence: ONE CTA of 512 threads per batch element. No clusters, no mbar.
//   Thread t0: j = t0 & 255 (output row), kh = t0 >> 8 (k-half).
//   Weights W_hh[j, kh*128 .. +128): 80 floats (40 f32x2) in registers,
//   48 floats (24 u64) in SMEM interleaved [24][512] (lane-consecutive LDS.64).
//   Per step:
//     all: FMA partial over own k-half (h broadcast-read from hb[p]);
//     kh=1: red[j] = part;            __syncthreads (bar1);
//     kh=0: v = xin + part + red[j]; tanh; hb[p^1][j] = h; out STG;
//                                     __syncthreads (bar2).
//   Race check: red write(t+1) vs read(t) split by bar2(t); hb[p^1] write(t)
//   (post-bar1) vs hb[p^1] read(t+1) (pre-bar1(t+1)) split by bar2(t).
// ---------------------------------------------------------------------------
#define NWREG 40   // u64 pairs in registers  (80 floats)
#define NWSM  24   // u64 pairs in SMEM       (48 floats)
// SMEM: Wsm 24*512 u64 = 98304 B | hb 2*256 f | red 256 f
#define REC_SMEM_BYTES (24 * 512 * 8 + 2 * 256 * 4 + 256 * 4)

template <bool TRANS>
__global__ __launch_bounds__(512, 1)
void rec_big_kernel(const float* __restrict__ xw,    // [B, T, H]
                    const float* __restrict__ Whh,   // [H, H]
                    float* __restrict__ out)
{
    extern __shared__ float smf[];
    uint64_t* Wsm = (uint64_t*)smf;            // [24][512]
    float*    hb  = smf + NWSM * 512 * 2;      // [2][256]
    float*    red = hb + 512;                  // [256]

    const int t0 = threadIdx.x;
    const int j  = t0 & 255;
    const int kh = t0 >> 8;
    const int b  = blockIdx.x;

    // Load weights: 40 u64 to regs, 24 u64 to SMEM (interleaved by pair idx).
    uint64_t w[NWREG];
    {
        const uint64_t* wrow = (const uint64_t*)(Whh + (size_t)j * HH + (kh << 7));
#pragma unroll
        for (int i = 0; i < NWREG; i++) w[i] = wrow[i];
#pragma unroll
        for (int i = 0; i < NWSM; i++) Wsm[i * 512 + t0] = wrow[NWREG + i];
    }
    hb[t0 & 511] = 0.0f;   // t0 covers [0,512) = both hb buffers
    __syncthreads();

    const float* xp = xw + (size_t)b * TT * HH + j;
    float xin = (kh == 0) ? xp[0] : 0.0f;

    int p = 0;
    for (int t = 0; t < TT; ++t) {
        const ulonglong2* h4 = (const ulonglong2*)(hb + p * 256 + (kh << 7));

        uint64_t a0 = 0ull, a1 = 0ull, a2 = 0ull, a3 = 0ull;
        // Register-resident weights: pairs 0..39  <->  h u64 0..39
#pragma unroll
        for (int i = 0; i < 20; i += 2) {
            ulonglong2 v0 = h4[i];
            ulonglong2 v1 = h4[i + 1];
            asm("fma.rn.f32x2 %0, %1, %2, %0;" : "+l"(a0) : "l"(w[2*i + 0]), "l"(v0.x));
            asm("fma.rn.f32x2 %0, %1, %2, %0;" : "+l"(a1) : "l"(w[2*i + 1]), "l"(v0.y));
            asm("fma.rn.f32x2 %0, %1, %2, %0;" : "+l"(a2) : "l"(w[2*i + 2]), "l"(v1.x));
            asm("fma.rn.f32x2 %0, %1, %2, %0;" : "+l"(a3) : "l"(w[2*i + 3]), "l"(v1.y));
        }
        // SMEM-resident weights: pairs 40..63  <->  h u64 40..63
#pragma unroll
        for (int i = 0; i < 12; i++) {
            ulonglong2 v = h4[20 + i];
            uint64_t w0 = Wsm[(2 * i)     * 512 + t0];
            uint64_t w1 = Wsm[(2 * i + 1) * 512 + t0];
            asm("fma.rn.f32x2 %0, %1, %2, %0;" : "+l"(a0) : "l"(w0), "l"(v.x));
            asm("fma.rn.f32x2 %0, %1, %2, %0;" : "+l"(a1) : "l"(w1), "l"(v.y));
        }
        asm("add.rn.f32x2 %0, %0, %1;" : "+l"(a0) : "l"(a1));
        asm("add.rn.f32x2 %0, %0, %1;" : "+l"(a2) : "l"(a3));
        asm("add.rn.f32x2 %0, %0, %1;" : "+l"(a0) : "l"(a2));
        uint32_t lo, hi;
        asm("mov.b64 {%0, %1}, %2;" : "=r"(lo), "=r"(hi) : "l"(a0));
        float part = __uint_as_float(lo) + __uint_as_float(hi);

        float xnext = 0.0f;
        if (kh) {
            red[j] = part;
        } else {
            xnext = (t + 1 < TT) ? xp[(size_t)(t + 1) * HH] : 0.0f;
        }
        __syncthreads();   // bar1: red ready; all reads of hb[p] done

        if (!kh) {
            float v = xin + part + red[j];
            float hval;
            asm("tanh.approx.f32 %0, %1;" : "=f"(hval) : "f"(v));
            hb[(p ^ 1) * 256 + j] = hval;
            if (TRANS) out[((size_t)b * HH + j) * TT + t] = hval;
            else       out[((size_t)b * TT + t) * HH + j] = hval;
            xin = xnext;
        }
        __syncthreads();   // bar2: new h visible; red consumable for overwrite
        p ^= 1;
    }
}

// ---------------------------------------------------------------------------
// Launch
// ---------------------------------------------------------------------------
extern "C" void kernel_launch(void* const* d_in, const int* in_sizes, int n_in,
                              void* d_out, int out_size)
{
    const float* x     = (const float*)d_in[0];
    const float* W_ih0 = (const float*)d_in[1];
    const float* W_hh0 = (const float*)d_in[2];
    const float* b_ih0 = (const float*)d_in[3];
    const float* b_hh0 = (const float*)d_in[4];
    const float* W_ih1 = (const float*)d_in[5];
    const float* W_hh1 = (const float*)d_in[6];
    const float* b_ih1 = (const float*)d_in[7];
    const float* b_hh1 = (const float*)d_in[8];
    float* out = (float*)d_out;

    float *bufA, *bufB;
    cudaGetSymbolAddress((void**)&bufA, g_bufA);
    cudaGetSymbolAddress((void**)&bufB, g_bufB);

    cudaFuncSetAttribute(rec_big_kernel<false>,
                         cudaFuncAttributeMaxDynamicSharedMemorySize, REC_SMEM_BYTES);
    cudaFuncSetAttribute(rec_big_kernel<true>,
                         cudaFuncAttributeMaxDynamicSharedMemorySize, REC_SMEM_BYTES);

    const int M = BB * TT;  // 65536

    // Layer 1 input projection: bufA = x @ W_ih0^T + (b_ih0 + b_hh0)
    gemm_bias_kernel<<<dim3(HH / 128, M / 128), 256>>>(
        x, W_ih0, b_ih0, b_hh0, bufA, M, HH, DD);

    // Layer 1 recurrence -> bufB = h1 [B,T,H]   (64 CTAs, 512 threads)
    rec_big_kernel<false><<<BB, 512, REC_SMEM_BYTES>>>(bufA, W_hh0, bufB);

    // Layer 2 input projection: bufA = h1 @ W_ih1^T + (b_ih1 + b_hh1)
    gemm_bias_kernel<<<dim3(HH / 128, M / 128), 256>>>(
        bufB, W_ih1, b_ih1, b_hh1, bufA, M, HH, HH);

    // Layer 2 recurrence -> out [B,H,T]
    rec_big_kernel<true><<<BB, 512, REC_SMEM_BYTES>>>(bufA, W_hh1, out);
}

// round 13
// speedup vs baseline: 1.1215x; 1.1215x over previous
#include <cuda_runtime.h>
#include <cuda_bf16.h>
#include <math.h>
#include <stdint.h>

// Problem constants
#define BB 64
#define TT 1024
#define DD 128
#define HH 256

// Scratch: layer-1 input projection only
__device__ float g_bufA[(size_t)BB * TT * HH];

// ---------------------------------------------------------------------------
// helpers
// ---------------------------------------------------------------------------
__device__ __forceinline__ uint32_t smem_u32(const void* p) {
    uint32_t a;
    asm("{ .reg .u64 t; cvta.to.shared.u64 t, %1; cvt.u32.u64 %0, t; }"
        : "=r"(a) : "l"(p));
    return a;
}
__device__ __forceinline__ void mbar_init(uint32_t addr, uint32_t count) {
    asm volatile("mbarrier.init.shared.b64 [%0], %1;" :: "r"(addr), "r"(count) : "memory");
}
__device__ __forceinline__ void mbar_wait_parity_acq_cluster(uint32_t addr, uint32_t parity) {
    asm volatile(
        "{\n\t"
        ".reg .pred P;\n\t"
        "WAIT_LOOP_%=:\n\t"
        "mbarrier.try_wait.parity.acquire.cluster.shared::cta.b64 P, [%0], %1, 0x989680;\n\t"
        "@!P bra WAIT_LOOP_%=;\n\t"
        "}"
        :: "r"(addr), "r"(parity) : "memory");
}

// ---------------------------------------------------------------------------
// GEMM1: C[M,N] = A[M,K] @ W[N,K]^T + b1 + b2  (R4 version — proven)
// ---------------------------------------------------------------------------
__global__ __launch_bounds__(256)
void gemm_bias_kernel(const float* __restrict__ A, const float* __restrict__ W,
                      const float* __restrict__ b1, const float* __restrict__ b2,
                      float* __restrict__ C, int M, int N, int K)
{
    __shared__ float As[16][128];
    __shared__ float Ws[16][128];
    const int m0 = blockIdx.y * 128, n0 = blockIdx.x * 128;
    const int tid = threadIdx.x, tr = tid >> 4, tc = tid & 15;

    uint64_t acc2[8][4];
#pragma unroll
    for (int i = 0; i < 8; i++)
#pragma unroll
        for (int l = 0; l < 4; l++) acc2[i][l] = 0ull;

    for (int k0 = 0; k0 < K; k0 += 16) {
#pragma unroll
        for (int it = 0; it < 2; it++) {
            int id = tid + it * 256, row = id >> 2, c4 = (id & 3) << 2;
            float4 v = *(const float4*)&A[(size_t)(m0 + row) * K + k0 + c4];
            As[c4 + 0][row] = v.x; As[c4 + 1][row] = v.y;
            As[c4 + 2][row] = v.z; As[c4 + 3][row] = v.w;
        }
#pragma unroll
        for (int it = 0; it < 2; it++) {
            int id = tid + it * 256, row = id >> 2, c4 = (id & 3) << 2;
            float4 v = *(const float4*)&W[(size_t)(n0 + row) * K + k0 + c4];
            Ws[c4 + 0][row] = v.x; Ws[c4 + 1][row] = v.y;
            Ws[c4 + 2][row] = v.z; Ws[c4 + 3][row] = v.w;
        }
        __syncthreads();
#pragma unroll
        for (int k = 0; k < 16; k++) {
            float a[8];
#pragma unroll
            for (int i = 0; i < 8; i++) a[i] = As[k][tr * 8 + i];
            uint64_t w2[4];
            const uint64_t* wp = (const uint64_t*)&Ws[k][tc * 8];
#pragma unroll
            for (int l = 0; l < 4; l++) w2[l] = wp[l];
#pragma unroll
            for (int i = 0; i < 8; i++) {
                uint64_t a2;
                asm("mov.b64 %0, {%1, %1};" : "=l"(a2) : "f"(a[i]));
#pragma unroll
                for (int l = 0; l < 4; l++)
                    asm("fma.rn.f32x2 %0, %1, %2, %0;" : "+l"(acc2[i][l]) : "l"(a2), "l"(w2[l]));
            }
        }
        __syncthreads();
    }
    float bb[8];
#pragma unroll
    for (int l = 0; l < 8; l++) { int n = n0 + tc * 8 + l; bb[l] = b1[n] + b2[n]; }
#pragma unroll
    for (int i = 0; i < 8; i++) {
        float r[8];
#pragma unroll
        for (int l = 0; l < 4; l++) {
            uint32_t lo, hi;
            asm("mov.b64 {%0, %1}, %2;" : "=r"(lo), "=r"(hi) : "l"(acc2[i][l]));
            r[2*l] = __uint_as_float(lo) + bb[2*l];
            r[2*l+1] = __uint_as_float(hi) + bb[2*l+1];
        }
        float* crow = &C[(size_t)(m0 + tr * 8 + i) * N + n0 + tc * 8];
        *(float4*)crow = make_float4(r[0], r[1], r[2], r[3]);
        *(float4*)(crow + 4) = make_float4(r[4], r[5], r[6], r[7]);
    }
}

// ---------------------------------------------------------------------------
// Fused 2-layer pipelined recurrence — deadlock/race-free version.
//  Round r in [0, TT]: L1 makes h1_r (r<TT); L2 makes h2_{r-1} (r>=1).
//  h1: TRIPLE buffered (hb0[3]); h1_r -> hb0[r%3]; round r reads hb0[(r-1)%3].
//  h2: double buffered (hb1[2]);  h2_{r-1} -> hb1[r&1]; read hb1[(r-1)&1].
//  mbars: ring-of-2 per direction. L1 phase q posted to peer mb0[q&1] at
//  round q; waited at round q+1 with parity (q>>1)&1. L2 phase q2 = r-1
//  posted to peer mb1[q2&1]; waited at round q2+2. No parity aliasing:
//  a slot's next phase is only posted after the previous one was consumed
//  (consumption precedes our next post in program order).
// SMEM: Wp[64][256]u64 | Wsm1[32][256]u64 | hb0[3][256] | hb1[2][256] |
//       red0[128] | red1[128] | mb0[2] mb1[2]
// ---------------------------------------------------------------------------
#define OFF_WP    0
#define OFF_WSM1  131072
#define OFF_HB0   196608                 // 3*1024 bytes
#define OFF_HB1   (OFF_HB0 + 3072)      // 2*1024
#define OFF_RED0  (OFF_HB1 + 2048)
#define OFF_RED1  (OFF_RED0 + 512)
#define OFF_MB    (OFF_RED1 + 512)      // 4 mbars * 8B
#define FUSED_SMEM (OFF_MB + 64)

__global__ __launch_bounds__(256, 1) __cluster_dims__(2, 1, 1)
void fused2_kernel(const float* __restrict__ xw0,
                   const float* __restrict__ Whh0,
                   const float* __restrict__ Whh1,
                   const float* __restrict__ Wih1,
                   const float* __restrict__ bih1,
                   const float* __restrict__ bhh1,
                   float* __restrict__ out)
{
    extern __shared__ __align__(16) char smraw[];
    uint64_t* Wp   = (uint64_t*)(smraw + OFF_WP);    // [64][256]
    uint64_t* Wsm1 = (uint64_t*)(smraw + OFF_WSM1);  // [32][256]
    float* hb0  = (float*)(smraw + OFF_HB0);         // [3][256]
    float* hb1  = (float*)(smraw + OFF_HB1);         // [2][256]
    float* red0 = (float*)(smraw + OFF_RED0);        // [128]
    float* red1 = (float*)(smraw + OFF_RED1);        // [128]
    uint64_t* mbarr = (uint64_t*)(smraw + OFF_MB);   // mb0[2], mb1[2]

    const int t0 = threadIdx.x;
    const int jl = t0 & 127;
    const int kh = t0 >> 7;
    uint32_t rank;
    asm("mov.u32 %0, %%cluster_ctarank;" : "=r"(rank));
    const int b = blockIdx.x >> 1;
    const int j = (int)rank * 128 + jl;
    const bool waiter = (kh != (int)rank);

    // Register weights: Whh0 full half-row (64 pairs), Whh1 pairs 0..31.
    uint64_t w0[64], w1r[32];
    {
        const uint64_t* r0p = (const uint64_t*)(Whh0 + (size_t)j * HH + (kh << 7));
#pragma unroll
        for (int i = 0; i < 64; i++) w0[i] = r0p[i];
        const uint64_t* r1p = (const uint64_t*)(Whh1 + (size_t)j * HH + (kh << 7));
#pragma unroll
        for (int i = 0; i < 32; i++) w1r[i] = r1p[i];
#pragma unroll
        for (int i = 0; i < 32; i++) Wsm1[i * 256 + t0] = r1p[32 + i];
        const uint64_t* rip = (const uint64_t*)(Wih1 + (size_t)j * HH + (kh << 7));
#pragma unroll 8
        for (int m = 0; m < 64; m++) Wp[m * 256 + t0] = rip[m];
    }
    // zero h buffers (t0 covers 256; 3+2 buffers of 256)
    hb0[t0] = 0.0f; hb0[256 + t0] = 0.0f; hb0[512 + t0] = 0.0f;
    hb1[t0] = 0.0f; hb1[256 + t0] = 0.0f;
    const uint32_t mb0a[2] = { smem_u32(&mbarr[0]), smem_u32(&mbarr[1]) };
    const uint32_t mb1a[2] = { smem_u32(&mbarr[2]), smem_u32(&mbarr[3]) };
    if (t0 == 0) {
        mbar_init(mb0a[0], 128); mbar_init(mb0a[1], 128);
        mbar_init(mb1a[0], 128); mbar_init(mb1a[1], 128);
    }
    __syncthreads();
    asm volatile("barrier.cluster.arrive.aligned;" ::: "memory");
    asm volatile("barrier.cluster.wait.aligned;"   ::: "memory");

    const uint32_t peer = rank ^ 1u;
    uint32_t r_h0[3], r_h1[2], r_mb0[2], r_mb1[2];
    {
        uint32_t a;
#pragma unroll
        for (int q = 0; q < 3; q++) {
            a = smem_u32(&hb0[q * 256 + j]);
            asm("mapa.shared::cluster.u32 %0, %1, %2;" : "=r"(r_h0[q]) : "r"(a), "r"(peer));
        }
#pragma unroll
        for (int q = 0; q < 2; q++) {
            a = smem_u32(&hb1[q * 256 + j]);
            asm("mapa.shared::cluster.u32 %0, %1, %2;" : "=r"(r_h1[q]) : "r"(a), "r"(peer));
            asm("mapa.shared::cluster.u32 %0, %1, %2;" : "=r"(r_mb0[q]) : "r"(mb0a[q]), "r"(peer));
            asm("mapa.shared::cluster.u32 %0, %1, %2;" : "=r"(r_mb1[q]) : "r"(mb1a[q]), "r"(peer));
        }
    }

    const float* xp = xw0 + (size_t)b * TT * HH + j;
    float xin = waiter ? xp[0] : 0.0f;
    const float ub = waiter ? (bih1[j] + bhh1[j]) : 0.0f;

    int wr = 0, rd = 2;   // hb0 write/read buffer indices (rd holds h1_{r-1})
    for (int r = 0; r <= TT; ++r) {
        const int pb = (r - 1) & 1;    // hb1 read buffer (h2_{r-2})

        float xnext = 0.0f;
        if (waiter && r + 1 < TT) xnext = xp[(size_t)(r + 1) * HH];

        if (waiter && r >= 1) {
            const int q = r - 1;
            mbar_wait_parity_acq_cluster(mb0a[q & 1], (uint32_t)((q >> 1) & 1));
        }

        // ---- L1: partial for h1_r ----
        float part0 = 0.0f;
        if (r < TT) {
            const ulonglong2* h4 = (const ulonglong2*)(hb0 + rd * 256 + (kh << 7));
            uint64_t a0 = 0ull, a1 = 0ull, a2 = 0ull, a3 = 0ull;
#pragma unroll
            for (int i = 0; i < 32; i += 2) {
                ulonglong2 v0 = h4[i];
                ulonglong2 v1 = h4[i + 1];
                asm("fma.rn.f32x2 %0, %1, %2, %0;" : "+l"(a0) : "l"(w0[2*i + 0]), "l"(v0.x));
                asm("fma.rn.f32x2 %0, %1, %2, %0;" : "+l"(a1) : "l"(w0[2*i + 1]), "l"(v0.y));
                asm("fma.rn.f32x2 %0, %1, %2, %0;" : "+l"(a2) : "l"(w0[2*i + 2]), "l"(v1.x));
                asm("fma.rn.f32x2 %0, %1, %2, %0;" : "+l"(a3) : "l"(w0[2*i + 3]), "l"(v1.y));
            }
            asm("add.rn.f32x2 %0, %0, %1;" : "+l"(a0) : "l"(a1));
            asm("add.rn.f32x2 %0, %0, %1;" : "+l"(a2) : "l"(a3));
            asm("add.rn.f32x2 %0, %0, %1;" : "+l"(a0) : "l"(a2));
            uint32_t lo, hi;
            asm("mov.b64 {%0, %1}, %2;" : "=r"(lo), "=r"(hi) : "l"(a0));
            part0 = __uint_as_float(lo) + __uint_as_float(hi);
            if (!waiter) red0[jl] = part0;
        }
        __syncthreads();   // A

        if (waiter && r < TT) {
            float v = xin + part0 + red0[jl];
            float h1v;
            asm("tanh.approx.f32 %0, %1;" : "=f"(h1v) : "f"(v));
            asm volatile("st.shared::cluster.f32 [%0], %1;" :: "r"(r_h0[wr]), "f"(h1v) : "memory");
            asm volatile("mbarrier.arrive.release.cluster.shared::cluster.b64 _, [%0];"
                         :: "r"(r_mb0[r & 1]) : "memory");
            hb0[wr * 256 + j] = h1v;
        }

        if (waiter && r >= 2) {
            const int q = r - 2;
            mbar_wait_parity_acq_cluster(mb1a[q & 1], (uint32_t)((q >> 1) & 1));
        }

        // ---- L2: partial for h2_{r-1} ----
        float part1;
        {
            uint64_t a0 = 0ull, a1 = 0ull, a2 = 0ull, a3 = 0ull;
            const ulonglong2* h4b = (const ulonglong2*)(hb1 + pb * 256 + (kh << 7));
#pragma unroll
            for (int i = 0; i < 16; i++) {
                ulonglong2 v = h4b[i];
                asm("fma.rn.f32x2 %0, %1, %2, %0;" : "+l"(a0) : "l"(w1r[2*i + 0]), "l"(v.x));
                asm("fma.rn.f32x2 %0, %1, %2, %0;" : "+l"(a1) : "l"(w1r[2*i + 1]), "l"(v.y));
            }
            const uint64_t* h2u = (const uint64_t*)(hb1 + pb * 256 + (kh << 7));
#pragma unroll 8
            for (int i = 0; i < 32; i++) {
                uint64_t wv = Wsm1[i * 256 + t0];
                asm("fma.rn.f32x2 %0, %1, %2, %0;" : "+l"(a2) : "l"(wv), "l"(h2u[32 + i]));
            }
            const uint64_t* h1u = (const uint64_t*)(hb0 + rd * 256 + (kh << 7));
#pragma unroll 8
            for (int m = 0; m < 64; m += 2) {
                uint64_t wa = Wp[m * 256 + t0];
                uint64_t wb = Wp[(m + 1) * 256 + t0];
                asm("fma.rn.f32x2 %0, %1, %2, %0;" : "+l"(a3) : "l"(wa), "l"(h1u[m]));
                asm("fma.rn.f32x2 %0, %1, %2, %0;" : "+l"(a0) : "l"(wb), "l"(h1u[m + 1]));
            }
            asm("add.rn.f32x2 %0, %0, %1;" : "+l"(a0) : "l"(a1));
            asm("add.rn.f32x2 %0, %0, %1;" : "+l"(a2) : "l"(a3));
            asm("add.rn.f32x2 %0, %0, %1;" : "+l"(a0) : "l"(a2));
            uint32_t lo, hi;
            asm("mov.b64 {%0, %1}, %2;" : "=r"(lo), "=r"(hi) : "l"(a0));
            part1 = __uint_as_float(lo) + __uint_as_float(hi);
            if (!waiter) red1[jl] = part1;
        }
        __syncthreads();   // B

        if (waiter && r >= 1) {
            float v = ub + part1 + red1[jl];
            float h2v;
            asm("tanh.approx.f32 %0, %1;" : "=f"(h2v) : "f"(v));
            asm volatile("st.shared::cluster.f32 [%0], %1;" :: "r"(r_h1[r & 1]), "f"(h2v) : "memory");
            asm volatile("mbarrier.arrive.release.cluster.shared::cluster.b64 _, [%0];"
                         :: "r"(r_mb1[(r - 1) & 1]) : "memory");
            hb1[(r & 1) * 256 + j] = h2v;
            out[((size_t)b * HH + j) * TT + (r - 1)] = h2v;
        }
        __syncthreads();   // C
        xin = xnext;
        rd = wr;
        wr = (wr == 2) ? 0 : wr + 1;
    }

    asm volatile("barrier.cluster.arrive.aligned;" ::: "memory");
    asm volatile("barrier.cluster.wait.aligned;"   ::: "memory");
}

// ---------------------------------------------------------------------------
// Launch
// ---------------------------------------------------------------------------
extern "C" void kernel_launch(void* const* d_in, const int* in_sizes, int n_in,
                              void* d_out, int out_size)
{
    const float* x     = (const float*)d_in[0];
    const float* W_ih0 = (const float*)d_in[1];
    const float* W_hh0 = (const float*)d_in[2];
    const float* b_ih0 = (const float*)d_in[3];
    const float* b_hh0 = (const float*)d_in[4];
    const float* W_ih1 = (const float*)d_in[5];
    const float* W_hh1 = (const float*)d_in[6];
    const float* b_ih1 = (const float*)d_in[7];
    const float* b_hh1 = (const float*)d_in[8];
    float* out = (float*)d_out;

    float* bufA;
    cudaGetSymbolAddress((void**)&bufA, g_bufA);

    cudaFuncSetAttribute(fused2_kernel,
                         cudaFuncAttributeMaxDynamicSharedMemorySize, FUSED_SMEM);

    const int M = BB * TT;  // 65536

    // Layer-1 input projection: bufA = x @ W_ih0^T + (b_ih0 + b_hh0)
    gemm_bias_kernel<<<dim3(HH / 128, M / 128), 256>>>(
        x, W_ih0, b_ih0, b_hh0, bufA, M, HH, DD);

    // Fused pipelined L1+L2 recurrences (h1 stays in SMEM; GEMM2 eliminated)
    fused2_kernel<<<BB * 2, 256, FUSED_SMEM>>>(
        bufA, W_hh0, W_hh1, W_ih1, b_ih1, b_hh1, out);
}

// round 14
// speedup vs baseline: 1.2388x; 1.1046x over previous
#include <cuda_runtime.h>
#include <cuda_bf16.h>
#include <math.h>
#include <stdint.h>

// Problem constants
#define BB 64
#define TT 1024
#define DD 128
#define HH 256

// Scratch ping-pong buffers [B*T*H] fp32
__device__ float g_bufA[(size_t)BB * TT * HH];
__device__ float g_bufB[(size_t)BB * TT * HH];

// ---------------------------------------------------------------------------
// GEMM: C[M,N] = A[M,K] @ W[N,K]^T + b1[n] + b2[n]
// BM=128, BN=128, BK=16, 256 threads, TM=8, TN=8, packed f32x2 accumulators.
// (R4 version — proven)
// ---------------------------------------------------------------------------
__global__ __launch_bounds__(256)
void gemm_bias_kernel(const float* __restrict__ A,
                      const float* __restrict__ W,
                      const float* __restrict__ b1,
                      const float* __restrict__ b2,
                      float* __restrict__ C,
                      int M, int N, int K)
{
    __shared__ float As[16][128];
    __shared__ float Ws[16][128];

    const int m0 = blockIdx.y * 128;
    const int n0 = blockIdx.x * 128;
    const int tid = threadIdx.x;
    const int tr = tid >> 4;
    const int tc = tid & 15;

    uint64_t acc2[8][4];
#pragma unroll
    for (int i = 0; i < 8; i++)
#pragma unroll
        for (int l = 0; l < 4; l++) acc2[i][l] = 0ull;

    for (int k0 = 0; k0 < K; k0 += 16) {
#pragma unroll
        for (int it = 0; it < 2; it++) {
            int id  = tid + it * 256;
            int row = id >> 2;
            int c4  = (id & 3) << 2;
            float4 v = *(const float4*)&A[(size_t)(m0 + row) * K + k0 + c4];
            As[c4 + 0][row] = v.x;
            As[c4 + 1][row] = v.y;
            As[c4 + 2][row] = v.z;
            As[c4 + 3][row] = v.w;
        }
#pragma unroll
        for (int it = 0; it < 2; it++) {
            int id  = tid + it * 256;
            int row = id >> 2;
            int c4  = (id & 3) << 2;
            float4 v = *(const float4*)&W[(size_t)(n0 + row) * K + k0 + c4];
            Ws[c4 + 0][row] = v.x;
            Ws[c4 + 1][row] = v.y;
            Ws[c4 + 2][row] = v.z;
            Ws[c4 + 3][row] = v.w;
        }
        __syncthreads();

#pragma unroll
        for (int k = 0; k < 16; k++) {
            float a[8];
#pragma unroll
            for (int i = 0; i < 8; i++) a[i] = As[k][tr * 8 + i];
            uint64_t w2[4];
            const uint64_t* wp = (const uint64_t*)&Ws[k][tc * 8];
#pragma unroll
            for (int l = 0; l < 4; l++) w2[l] = wp[l];
#pragma unroll
            for (int i = 0; i < 8; i++) {
                uint64_t a2;
                asm("mov.b64 %0, {%1, %1};" : "=l"(a2) : "f"(a[i]));
#pragma unroll
                for (int l = 0; l < 4; l++)
                    asm("fma.rn.f32x2 %0, %1, %2, %0;"
                        : "+l"(acc2[i][l]) : "l"(a2), "l"(w2[l]));
            }
        }
        __syncthreads();
    }

    float bb[8];
#pragma unroll
    for (int l = 0; l < 8; l++) {
        int n = n0 + tc * 8 + l;
        bb[l] = b1[n] + b2[n];
    }
#pragma unroll
    for (int i = 0; i < 8; i++) {
        float r[8];
#pragma unroll
        for (int l = 0; l < 4; l++) {
            uint32_t lo, hi;
            asm("mov.b64 {%0, %1}, %2;" : "=r"(lo), "=r"(hi) : "l"(acc2[i][l]));
            r[2 * l]     = __uint_as_float(lo) + bb[2 * l];
            r[2 * l + 1] = __uint_as_float(hi) + bb[2 * l + 1];
        }
        float* crow = &C[(size_t)(m0 + tr * 8 + i) * N + n0 + tc * 8];
        *(float4*)crow       = make_float4(r[0], r[1], r[2], r[3]);
        *(float4*)(crow + 4) = make_float4(r[4], r[5], r[6], r[7]);
    }
}

// ---------------------------------------------------------------------------
// Recurrence: ONE CTA of 256 threads per batch element. No cluster, no mbar.
//   Thread j owns output row j: full 256-term dot per step.
//   Weights W_hh[j, :]: k-floats [0,160) = 80 u64 in REGISTERS;
//                       k-floats [160,256) = 24 ulonglong2 in SMEM [24][256]
//                       (lane-stride-16B LDS.128, conflict-free).
//   h double-buffered in SMEM, read as broadcast LDS.128 (ulonglong2).
//   Per step: ONE __syncthreads. Correctness of buffer reuse:
//   write hb[p^1] (step t) vs read hb[p^1] (step t+1) split by bar_t;
//   write hb[p] (step t+1, after bar_t) vs read hb[p] (step t, before bar_t). OK.
// ---------------------------------------------------------------------------
#define NSMW 24   // ulonglong2 smem weights per thread (96 floats)
#define REC_SMEM_BYTES (NSMW * 256 * 16 + 2 * 256 * 4)

template <bool TRANS>
__global__ __launch_bounds__(256, 1)
void rec_split_kernel(const float* __restrict__ xw,    // [B, T, H]
                      const float* __restrict__ Whh,   // [H, H]
                      float* __restrict__ out)
{
    extern __shared__ __align__(16) char smraw[];
    ulonglong2* Wsm = (ulonglong2*)smraw;                 // [24][256]
    float* hb = (float*)(smraw + NSMW * 256 * 16);        // [2][256]

    const int t0 = threadIdx.x;   // == output row j
    const int b  = blockIdx.x;

    // Load weights: 80 u64 (160 floats) to regs, 24 u128 (96 floats) to SMEM.
    uint64_t w[80];
    {
        const uint64_t* wrow64 = (const uint64_t*)(Whh + (size_t)t0 * HH);
#pragma unroll
        for (int i = 0; i < 80; i++) w[i] = wrow64[i];
        const ulonglong2* wrow2 = (const ulonglong2*)wrow64;
#pragma unroll
        for (int i = 0; i < NSMW; i++) Wsm[i * 256 + t0] = wrow2[40 + i];
    }
    hb[t0] = 0.0f;
    hb[256 + t0] = 0.0f;
    __syncthreads();

    const float* xp = xw + (size_t)b * TT * HH + t0;
    float xin = xp[0];

    int p = 0;
    for (int t = 0; t < TT; ++t) {
        float xnext = (t + 1 < TT) ? xp[(size_t)(t + 1) * HH] : 0.0f;

        const ulonglong2* h2 = (const ulonglong2*)(hb + p * 256);  // 64 u64-pairs
        uint64_t a0 = 0ull, a1 = 0ull, a2 = 0ull, a3 = 0ull;

        // SMEM-weight part first (k u64 idx 80..127): LDS pipelines ahead.
#pragma unroll
        for (int i = 0; i < NSMW; i += 2) {
            ulonglong2 wv0 = Wsm[(i)     * 256 + t0];
            ulonglong2 wv1 = Wsm[(i + 1) * 256 + t0];
            ulonglong2 hv0 = h2[40 + i];
            ulonglong2 hv1 = h2[41 + i];
            asm("fma.rn.f32x2 %0, %1, %2, %0;" : "+l"(a0) : "l"(wv0.x), "l"(hv0.x));
            asm("fma.rn.f32x2 %0, %1, %2, %0;" : "+l"(a1) : "l"(wv0.y), "l"(hv0.y));
            asm("fma.rn.f32x2 %0, %1, %2, %0;" : "+l"(a2) : "l"(wv1.x), "l"(hv1.x));
            asm("fma.rn.f32x2 %0, %1, %2, %0;" : "+l"(a3) : "l"(wv1.y), "l"(hv1.y));
        }
        // Register-weight part (k u64 idx 0..79)
#pragma unroll
        for (int i = 0; i < 40; i += 2) {
            ulonglong2 v0 = h2[i];
            ulonglong2 v1 = h2[i + 1];
            asm("fma.rn.f32x2 %0, %1, %2, %0;" : "+l"(a0) : "l"(w[2*i + 0]), "l"(v0.x));
            asm("fma.rn.f32x2 %0, %1, %2, %0;" : "+l"(a1) : "l"(w[2*i + 1]), "l"(v0.y));
            asm("fma.rn.f32x2 %0, %1, %2, %0;" : "+l"(a2) : "l"(w[2*i + 2]), "l"(v1.x));
            asm("fma.rn.f32x2 %0, %1, %2, %0;" : "+l"(a3) : "l"(w[2*i + 3]), "l"(v1.y));
        }
        asm("add.rn.f32x2 %0, %0, %1;" : "+l"(a0) : "l"(a1));
        asm("add.rn.f32x2 %0, %0, %1;" : "+l"(a2) : "l"(a3));
        asm("add.rn.f32x2 %0, %0, %1;" : "+l"(a0) : "l"(a2));
        uint32_t lo, hi;
        asm("mov.b64 {%0, %1}, %2;" : "=r"(lo), "=r"(hi) : "l"(a0));
        float part = __uint_as_float(lo) + __uint_as_float(hi);

        float v = xin + part;
        float hval;
        asm("tanh.approx.f32 %0, %1;" : "=f"(hval) : "f"(v));
        hb[(p ^ 1) * 256 + t0] = hval;
        if (TRANS) out[((size_t)b * HH + t0) * TT + t] = hval;
        else       out[((size_t)b * TT + t) * HH + t0] = hval;
        xin = xnext;
        __syncthreads();
        p ^= 1;
    }
}

// ---------------------------------------------------------------------------
// Launch
// ---------------------------------------------------------------------------
extern "C" void kernel_launch(void* const* d_in, const int* in_sizes, int n_in,
                              void* d_out, int out_size)
{
    const float* x     = (const float*)d_in[0];
    const float* W_ih0 = (const float*)d_in[1];
    const float* W_hh0 = (const float*)d_in[2];
    const float* b_ih0 = (const float*)d_in[3];
    const float* b_hh0 = (const float*)d_in[4];
    const float* W_ih1 = (const float*)d_in[5];
    const float* W_hh1 = (const float*)d_in[6];
    const float* b_ih1 = (const float*)d_in[7];
    const float* b_hh1 = (const float*)d_in[8];
    float* out = (float*)d_out;

    float *bufA, *bufB;
    cudaGetSymbolAddress((void**)&bufA, g_bufA);
    cudaGetSymbolAddress((void**)&bufB, g_bufB);

    cudaFuncSetAttribute(rec_split_kernel<false>,
                         cudaFuncAttributeMaxDynamicSharedMemorySize, REC_SMEM_BYTES);
    cudaFuncSetAttribute(rec_split_kernel<true>,
                         cudaFuncAttributeMaxDynamicSharedMemorySize, REC_SMEM_BYTES);

    const int M = BB * TT;  // 65536

    // Layer 1 input projection: bufA = x @ W_ih0^T + (b_ih0 + b_hh0)
    gemm_bias_kernel<<<dim3(HH / 128, M / 128), 256>>>(
        x, W_ih0, b_ih0, b_hh0, bufA, M, HH, DD);

    // Layer 1 recurrence -> bufB = h1 [B,T,H]   (64 CTAs, 256 threads)
    rec_split_kernel<false><<<BB, 256, REC_SMEM_BYTES>>>(bufA, W_hh0, bufB);

    // Layer 2 input projection: bufA = h1 @ W_ih1^T + (b_ih1 + b_hh1)
    gemm_bias_kernel<<<dim3(HH / 128, M / 128), 256>>>(
        bufB, W_ih1, b_ih1, b_hh1, bufA, M, HH, HH);

    // Layer 2 recurrence -> out [B,H,T]
    rec_split_kernel<true><<<BB, 256, REC_SMEM_BYTES>>>(bufA, W_hh1, out);
}